// round 1
// baseline (speedup 1.0000x reference)
#include <cuda_runtime.h>
#include <math_constants.h>

// Normalized prototypes, transposed + k-pair interleaved:
// float index = (c>>1)*1024 + p*2 + (c&1)   [kk rows of 512 protos x 2 channels]
__device__ float g_pnT2[128 * 1024];

// ---------------------------------------------------------------------------
// Pre-kernel: L2-normalize prototype rows (torch F.normalize semantics:
// p / max(||p||, 1e-12)) and write transposed, k-pair-interleaved layout.
// ---------------------------------------------------------------------------
__global__ void proto_prep_kernel(const float* __restrict__ proto) {
    __shared__ float sred[8];
    const int p = blockIdx.x;    // 0..511
    const int c = threadIdx.x;   // 0..255
    float v = proto[(p << 8) + c];
    float ss = v * v;
    #pragma unroll
    for (int s = 16; s >= 1; s >>= 1)
        ss += __shfl_xor_sync(0xffffffffu, ss, s);
    if ((c & 31) == 0) sred[c >> 5] = ss;
    __syncthreads();
    float tot = 0.f;
    #pragma unroll
    for (int w = 0; w < 8; ++w) tot += sred[w];
    const float denom = fmaxf(sqrtf(tot), 1e-12f);
    const float pn = v / denom;
    g_pnT2[((c >> 1) << 10) + (p << 1) + (c & 1)] = pn;
}

// ---------------------------------------------------------------------------
// Main kernel: per block, 128 pixels x 512 protos x 256 channels fp32 GEMM
// via packed fma.rn.f32x2 (k-pair interleaved), fused argmax + gather.
// ---------------------------------------------------------------------------
__global__ __launch_bounds__(256, 1)
void protomatch_kernel(const float* __restrict__ x,
                       const float* __restrict__ proto,
                       float* __restrict__ out,
                       long long out_size)
{
    extern __shared__ float sm[];
    float* Xs = sm;            // 32768 floats: [kk(128)] rows of 128 pixel-pairs (256 f)
    float* Ps = sm + 32768;    //  4096 floats: [kkl(16)] rows of 128 proto-pairs (256 f)

    const int tid = threadIdx.x;
    const int m0  = blockIdx.x << 7;   // first pixel of tile
    const int b   = m0 >> 10;          // batch
    const int n0  = m0 & 1023;         // pixel-in-batch offset (multiple of 128)

    // ---- load X tile (128 pixels x 256 ch) into k-pair-interleaved smem ----
    const float4* Xg = reinterpret_cast<const float4*>(x) + (b * 65536 + (n0 >> 2));
    #pragma unroll
    for (int i = 0; i < 32; ++i) {
        int e4 = tid + (i << 8);
        int c  = e4 >> 5;          // channel 0..255
        int m4 = e4 & 31;          // float4 group of pixels
        float4 v = Xg[c * 256 + m4];
        float* dst = Xs + ((c >> 1) << 8) + (c & 1) + (m4 << 3);
        dst[0] = v.x; dst[2] = v.y; dst[4] = v.z; dst[6] = v.w;
    }

    const int ty = tid >> 4;   // 0..15 : pixel group (8 pixels)
    const int tx = tid & 15;   // 0..15 : proto group (8 protos)

    float bestV[8];
    int   bestI[8];
    #pragma unroll
    for (int i = 0; i < 8; ++i) { bestV[i] = -CUDART_INF_F; bestI[i] = 0; }

    for (int pc = 0; pc < 4; ++pc) {           // 4 chunks of 128 protos
        unsigned long long acc[8][8];
        #pragma unroll
        for (int i = 0; i < 8; ++i)
            #pragma unroll
            for (int j = 0; j < 8; ++j) acc[i][j] = 0ull;

        for (int ks = 0; ks < 8; ++ks) {       // 8 steps of 16 k-pairs (32 channels)
            __syncthreads();                    // protect Ps from previous step
            const float4* Pg = reinterpret_cast<const float4*>(g_pnT2)
                             + (ks * 16) * 256 + pc * 64;
            float4* Ps4 = reinterpret_cast<float4*>(Ps);
            #pragma unroll
            for (int i = 0; i < 4; ++i) {
                int e4  = tid + (i << 8);
                int kkl = e4 >> 6;
                int p4  = e4 & 63;
                Ps4[(kkl << 6) + p4] = Pg[kkl * 256 + p4];
            }
            __syncthreads();

            #pragma unroll
            for (int kk = 0; kk < 16; ++kk) {
                const ulonglong2* xr = reinterpret_cast<const ulonglong2*>(
                        Xs + ((ks * 16 + kk) << 8)) + (ty << 2);
                const ulonglong2* pr = reinterpret_cast<const ulonglong2*>(
                        Ps + (kk << 8)) + (tx << 2);
                ulonglong2 xv0 = xr[0], xv1 = xr[1], xv2 = xr[2], xv3 = xr[3];
                ulonglong2 pv0 = pr[0], pv1 = pr[1], pv2 = pr[2], pv3 = pr[3];
                unsigned long long xp[8] = {xv0.x, xv0.y, xv1.x, xv1.y,
                                            xv2.x, xv2.y, xv3.x, xv3.y};
                unsigned long long pp[8] = {pv0.x, pv0.y, pv1.x, pv1.y,
                                            pv2.x, pv2.y, pv3.x, pv3.y};
                #pragma unroll
                for (int i = 0; i < 8; ++i)
                    #pragma unroll
                    for (int j = 0; j < 8; ++j)
                        asm("fma.rn.f32x2 %0, %1, %2, %0;"
                            : "+l"(acc[i][j])
                            : "l"(xp[i]), "l"(pp[j]));
            }
        }

        // fold (even-k, odd-k) partials and update running argmax
        #pragma unroll
        for (int i = 0; i < 8; ++i) {
            #pragma unroll
            for (int j = 0; j < 8; ++j) {
                union { unsigned long long u; float2 f; } cv;
                cv.u = acc[i][j];
                float s = cv.f.x + cv.f.y;
                int idx = (pc << 7) + (tx << 3) + j;
                if (s > bestV[i]) { bestV[i] = s; bestI[i] = idx; }
            }
        }
    }

    __syncthreads();   // done reading Ps; reuse it as index staging
    int* sIdx = reinterpret_cast<int*>(Ps);

    // argmax reduction over the 16 tx-lanes (ties -> smallest index, matching
    // jnp.argmax first-occurrence semantics)
    #pragma unroll
    for (int i = 0; i < 8; ++i) {
        float v = bestV[i];
        int  ix = bestI[i];
        #pragma unroll
        for (int s = 8; s >= 1; s >>= 1) {
            float ov = __shfl_xor_sync(0xffffffffu, v, s);
            int   oi = __shfl_xor_sync(0xffffffffu, ix, s);
            if (ov > v || (ov == v && oi < ix)) { v = ov; ix = oi; }
        }
        if (tx == 0) sIdx[(ty << 3) + i] = ix;
    }
    __syncthreads();

    // ---- gather UNnormalized prototypes, write recon [B,C,H,W] coalesced ----
    const int n4 = tid & 31;   // float4 column within the 128-pixel tile
    const int co = tid >> 5;   // channel phase 0..7
    const int p0 = sIdx[(n4 << 2) + 0];
    const int p1 = sIdx[(n4 << 2) + 1];
    const int p2 = sIdx[(n4 << 2) + 2];
    const int p3 = sIdx[(n4 << 2) + 3];
    const float* r0 = proto + (p0 << 8);
    const float* r1 = proto + (p1 << 8);
    const float* r2 = proto + (p2 << 8);
    const float* r3 = proto + (p3 << 8);
    float4* Og = reinterpret_cast<float4*>(out) + (b * 65536 + (n0 >> 2) + n4);
    #pragma unroll 4
    for (int c = co; c < 256; c += 8) {
        float4 w = make_float4(r0[c], r1[c], r2[c], r3[c]);
        Og[c * 256] = w;
    }

    // indices output (second reference output), as float in the tail
    if (out_size > 16777216LL && tid < 128)
        out[16777216 + m0 + tid] = (float)sIdx[tid];
}

// ---------------------------------------------------------------------------
extern "C" void kernel_launch(void* const* d_in, const int* in_sizes, int n_in,
                              void* d_out, int out_size)
{
    const float* x     = (const float*)d_in[0];
    const float* proto = (const float*)d_in[1];
    // defensive input-order detection: prototype_bank has 512*256 elements
    if (n_in >= 2 && in_sizes[0] == 512 * 256 && in_sizes[1] != 512 * 256) {
        proto = (const float*)d_in[0];
        x     = (const float*)d_in[1];
    }
    float* out = (float*)d_out;

    proto_prep_kernel<<<512, 256>>>(proto);

    cudaFuncSetAttribute(protomatch_kernel,
                         cudaFuncAttributeMaxDynamicSharedMemorySize, 147456);
    protomatch_kernel<<<512, 256, 147456>>>(x, proto, out, (long long)out_size);
}

// round 2
// speedup vs baseline: 1.6606x; 1.6606x over previous
#include <cuda_runtime.h>
#include <math_constants.h>

// Normalized prototypes, transposed + k-pair interleaved:
// float index = (c>>1)*1024 + p*2 + (c&1)   [128 kk-rows of 512 protos x 2 ch]
__device__ float g_pnT2[128 * 1024];

// ---------------------------------------------------------------------------
// Pre-kernel: L2-normalize prototype rows (p / max(||p||, 1e-12)) and write
// transposed, k-pair-interleaved layout.
// ---------------------------------------------------------------------------
__global__ void proto_prep_kernel(const float* __restrict__ proto) {
    __shared__ float sred[8];
    const int p = blockIdx.x;    // 0..511
    const int c = threadIdx.x;   // 0..255
    float v = proto[(p << 8) + c];
    float ss = v * v;
    #pragma unroll
    for (int s = 16; s >= 1; s >>= 1)
        ss += __shfl_xor_sync(0xffffffffu, ss, s);
    if ((c & 31) == 0) sred[c >> 5] = ss;
    __syncthreads();
    float tot = 0.f;
    #pragma unroll
    for (int w = 0; w < 8; ++w) tot += sred[w];
    const float denom = fmaxf(sqrtf(tot), 1e-12f);
    g_pnT2[((c >> 1) << 10) + (p << 1) + (c & 1)] = v / denom;
}

// ---------------------------------------------------------------------------
// cp.async prefetch of one P chunk (16 kk-rows x 128 proto-pairs = 16KB)
// into double buffer slot (t&1).
// ---------------------------------------------------------------------------
__device__ __forceinline__ void prefetch_P(float* Ps, int t, int tid) {
    const int pc = t >> 3;
    const int ks = t & 7;
    const float4* Pg = reinterpret_cast<const float4*>(g_pnT2)
                     + (ks * 16) * 256 + pc * 64;
    float4* dst4 = reinterpret_cast<float4*>(Ps + ((t & 1) << 12));
    #pragma unroll
    for (int i = 0; i < 4; ++i) {
        int e4  = tid + (i << 8);
        int kkl = e4 >> 6;      // 0..15
        int p4  = e4 & 63;      // 0..63
        const float4* src = Pg + kkl * 256 + p4;
        float4* d = dst4 + (kkl << 6) + p4;
        unsigned saddr = (unsigned)__cvta_generic_to_shared(d);
        asm volatile("cp.async.cg.shared.global [%0], [%1], 16;\n"
                     :: "r"(saddr), "l"(src));
    }
}

// ---------------------------------------------------------------------------
// Main kernel: per block, 128 pixels x 512 protos x 256 channels fp32 GEMM
// via packed fma.rn.f32x2 (k-pair interleaved), fused argmax + gather.
// ---------------------------------------------------------------------------
__global__ __launch_bounds__(256, 1)
void protomatch_kernel(const float* __restrict__ x,
                       const float* __restrict__ proto,
                       float* __restrict__ out,
                       long long out_size)
{
    extern __shared__ float sm[];
    float* Xs = sm;            // 32768 floats: 128 kk-rows of 128 pixel-pairs
    float* Ps = sm + 32768;    //  8192 floats: double buffer of 16 kk-rows x 128 pairs

    const int tid = threadIdx.x;
    const int m0  = blockIdx.x << 7;   // first pixel of tile
    const int b   = m0 >> 10;          // batch
    const int n0  = m0 & 1023;         // pixel-in-batch offset (multiple of 128)

    // ---- load X tile (128 pixels x 256 ch) into k-pair-interleaved smem ----
    const float4* Xg = reinterpret_cast<const float4*>(x) + (b * 65536 + (n0 >> 2));
    #pragma unroll
    for (int i = 0; i < 32; ++i) {
        int e4 = tid + (i << 8);
        int c  = e4 >> 5;          // channel 0..255
        int m4 = e4 & 31;          // float4 group of pixels
        float4 v = Xg[c * 256 + m4];
        float* dst = Xs + ((c >> 1) << 8) + (c & 1) + (m4 << 3);
        dst[0] = v.x; dst[2] = v.y; dst[4] = v.z; dst[6] = v.w;
    }

    const int ty = tid >> 4;   // 0..15 : pixel group (8 pixels)
    const int tx = tid & 15;   // 0..15 : proto lane (protos tx + 16j)

    float bestV[8];
    int   bestI[8];
    #pragma unroll
    for (int i = 0; i < 8; ++i) { bestV[i] = -CUDART_INF_F; bestI[i] = 0; }

    // prime the P pipeline
    prefetch_P(Ps, 0, tid);
    asm volatile("cp.async.commit_group;\n");

    int t = 0;
    for (int pc = 0; pc < 4; ++pc) {           // 4 chunks of 128 protos
        unsigned long long acc[8][8];
        #pragma unroll
        for (int i = 0; i < 8; ++i)
            #pragma unroll
            for (int j = 0; j < 8; ++j) acc[i][j] = 0ull;

        for (int ks = 0; ks < 8; ++ks, ++t) {  // 8 steps of 16 k-pairs
            __syncthreads();                    // all readers done with buf[(t+1)&1]
            if (t + 1 < 32) {
                prefetch_P(Ps, t + 1, tid);
                asm volatile("cp.async.commit_group;\n");
                asm volatile("cp.async.wait_group 1;\n");  // buf t complete
            } else {
                asm volatile("cp.async.wait_group 0;\n");
            }
            __syncthreads();                    // buf t visible to all

            const float* P = Ps + ((t & 1) << 12);

            #pragma unroll
            for (int kk = 0; kk < 16; ++kk) {
                const unsigned long long* xr =
                    reinterpret_cast<const unsigned long long*>(
                        Xs + ((ks * 16 + kk) << 8)) + (ty << 3);
                const unsigned long long* pr =
                    reinterpret_cast<const unsigned long long*>(P + (kk << 8));
                unsigned long long xp[8], pp[8];
                #pragma unroll
                for (int i = 0; i < 8; ++i) xp[i] = xr[i];
                #pragma unroll
                for (int j = 0; j < 8; ++j) pp[j] = pr[tx + (j << 4)];
                #pragma unroll
                for (int i = 0; i < 8; ++i)
                    #pragma unroll
                    for (int j = 0; j < 8; ++j)
                        asm("fma.rn.f32x2 %0, %1, %2, %0;"
                            : "+l"(acc[i][j])
                            : "l"(xp[i]), "l"(pp[j]));
            }
        }

        // fold (even-k, odd-k) partials and update running argmax
        #pragma unroll
        for (int i = 0; i < 8; ++i) {
            #pragma unroll
            for (int j = 0; j < 8; ++j) {
                union { unsigned long long u; float2 f; } cv;
                cv.u = acc[i][j];
                float s = cv.f.x + cv.f.y;
                int idx = (pc << 7) + tx + (j << 4);
                if (s > bestV[i]) { bestV[i] = s; bestI[i] = idx; }
            }
        }
    }

    __syncthreads();   // compute done; reuse Xs as index staging
    int* sIdx = reinterpret_cast<int*>(Xs);

    // argmax reduction over the 16 tx-lanes (ties -> smallest index, matching
    // jnp.argmax first-occurrence semantics)
    #pragma unroll
    for (int i = 0; i < 8; ++i) {
        float v = bestV[i];
        int  ix = bestI[i];
        #pragma unroll
        for (int s = 8; s >= 1; s >>= 1) {
            float ov = __shfl_xor_sync(0xffffffffu, v, s);
            int   oi = __shfl_xor_sync(0xffffffffu, ix, s);
            if (ov > v || (ov == v && oi < ix)) { v = ov; ix = oi; }
        }
        if (tx == 0) sIdx[(ty << 3) + i] = ix;
    }
    __syncthreads();

    // ---- gather UNnormalized prototypes, write recon [B,C,H,W] coalesced ----
    const int n4 = tid & 31;   // float4 column within the 128-pixel tile
    const int co = tid >> 5;   // channel phase 0..7
    const int p0 = sIdx[(n4 << 2) + 0];
    const int p1 = sIdx[(n4 << 2) + 1];
    const int p2 = sIdx[(n4 << 2) + 2];
    const int p3 = sIdx[(n4 << 2) + 3];
    const float* r0 = proto + (p0 << 8);
    const float* r1 = proto + (p1 << 8);
    const float* r2 = proto + (p2 << 8);
    const float* r3 = proto + (p3 << 8);
    float4* Og = reinterpret_cast<float4*>(out) + (b * 65536 + (n0 >> 2) + n4);
    #pragma unroll 4
    for (int c = co; c < 256; c += 8) {
        float4 w = make_float4(r0[c], r1[c], r2[c], r3[c]);
        Og[c * 256] = w;
    }

    // indices output (second reference output), as float in the tail
    if (out_size > 16777216LL && tid < 128)
        out[16777216 + m0 + tid] = (float)sIdx[tid];
}

// ---------------------------------------------------------------------------
extern "C" void kernel_launch(void* const* d_in, const int* in_sizes, int n_in,
                              void* d_out, int out_size)
{
    const float* x     = (const float*)d_in[0];
    const float* proto = (const float*)d_in[1];
    if (n_in >= 2 && in_sizes[0] == 512 * 256 && in_sizes[1] != 512 * 256) {
        proto = (const float*)d_in[0];
        x     = (const float*)d_in[1];
    }
    float* out = (float*)d_out;

    proto_prep_kernel<<<512, 256>>>(proto);

    cudaFuncSetAttribute(protomatch_kernel,
                         cudaFuncAttributeMaxDynamicSharedMemorySize, 163840);
    protomatch_kernel<<<512, 256, 163840>>>(x, proto, out, (long long)out_size);
}